// round 7
// baseline (speedup 1.0000x reference)
#include <cuda_runtime.h>
#include <cstdint>
#include <math.h>

#define Tn 4096
#define Hn 1024
#define In 2816
#define En 7

// ---------------- static scratch ----------------
__device__ float xr_buf[(size_t)Tn * Hn];
__device__ float wgs_r[(size_t)In * Hn];
__device__ float wus_r[(size_t)In * Hn];
__device__ float wds_r[(size_t)Hn * In];
__device__ float wg_r[(size_t)En * In * Hn];
__device__ float wu_r[(size_t)En * In * Hn];
__device__ float wd_r[(size_t)En * Hn * In];
__device__ float g_buf[(size_t)Tn * In];
__device__ float u_buf[(size_t)Tn * In];
__device__ float g2_buf[(size_t)2 * Tn * In];
__device__ float u2_buf[(size_t)2 * Tn * In];
__device__ float y2_buf[(size_t)2 * Tn * Hn];
__device__ float dummy_logits[(size_t)Tn * En];

__device__ int   d_counts[En];
__device__ int   d_offsets[En];
__device__ int   d_cursor[En];
__device__ int   d_sel[Tn * 2];
__device__ float d_wgt[Tn * 2];
__device__ int   d_slot_token[2 * Tn];
__device__ int   d_token_slot[Tn * 2];

// ---------------- PTX helpers (portable, sm_80+) ----------------
__device__ __forceinline__ uint32_t smem_u32(const void* p) {
    uint32_t a;
    asm("{ .reg .u64 t; cvta.to.shared.u64 t, %1; cvt.u32.u64 %0, t; }" : "=r"(a) : "l"(p));
    return a;
}
__device__ __forceinline__ float to_tf32(float v) {
    uint32_t r; asm("cvt.rna.tf32.f32 %0, %1;" : "=r"(r) : "f"(v));
    return __uint_as_float(r);
}
__device__ __forceinline__ void cpasync16(uint32_t dst, const void* src) {
    asm volatile("cp.async.cg.shared.global [%0], [%1], 16;" :: "r"(dst), "l"(src) : "memory");
}
__device__ __forceinline__ void cpcommit() {
    asm volatile("cp.async.commit_group;" ::: "memory");
}
__device__ __forceinline__ void cpwait(int n) {
    if (n <= 0)      asm volatile("cp.async.wait_group 0;" ::: "memory");
    else if (n == 1) asm volatile("cp.async.wait_group 1;" ::: "memory");
    else             asm volatile("cp.async.wait_group 2;" ::: "memory");
}

__device__ __forceinline__ void ldsm_x4(uint32_t* r, uint32_t addr) {
    asm volatile("ldmatrix.sync.aligned.m8n8.x4.shared.b16 {%0,%1,%2,%3}, [%4];"
        : "=r"(r[0]), "=r"(r[1]), "=r"(r[2]), "=r"(r[3]) : "r"(addr));
}
__device__ __forceinline__ void ldsm_x2(uint32_t* r, uint32_t addr) {
    asm volatile("ldmatrix.sync.aligned.m8n8.x2.shared.b16 {%0,%1}, [%2];"
        : "=r"(r[0]), "=r"(r[1]) : "r"(addr));
}

__device__ __forceinline__ void mma8(float* c, const uint32_t* a, const uint32_t* b) {
    asm volatile(
        "mma.sync.aligned.m16n8k8.row.col.f32.tf32.tf32.f32 "
        "{%0,%1,%2,%3}, {%4,%5,%6,%7}, {%8,%9}, {%0,%1,%2,%3};\n"
        : "+f"(c[0]), "+f"(c[1]), "+f"(c[2]), "+f"(c[3])
        : "r"(a[0]), "r"(a[1]), "r"(a[2]), "r"(a[3]),
          "r"(b[0]), "r"(b[1]));
}

// ---------------- small kernels ----------------
__global__ void init_kernel() {
    int i = threadIdx.x;
    if (i < En) { d_counts[i] = 0; d_cursor[i] = 0; }
}

__global__ void round_kernel(const float* __restrict__ s, float* __restrict__ d, size_t n4) {
    size_t i = (size_t)blockIdx.x * blockDim.x + threadIdx.x;
    if (i >= n4) return;
    float4 v = reinterpret_cast<const float4*>(s)[i];
    v.x = to_tf32(v.x); v.y = to_tf32(v.y); v.z = to_tf32(v.z); v.w = to_tf32(v.w);
    reinterpret_cast<float4*>(d)[i] = v;
}

__global__ void routing_kernel(const float* __restrict__ x,
                               const float* __restrict__ Wr,
                               float* __restrict__ logits_out,
                               float* __restrict__ xr) {
    int warp = threadIdx.x >> 5;
    int lane = threadIdx.x & 31;
    int t = blockIdx.x * (blockDim.x >> 5) + warp;
    if (t >= Tn) return;
    const float* xrow = x + (size_t)t * Hn;
    float acc[En];
#pragma unroll
    for (int e = 0; e < En; e++) acc[e] = 0.f;
    for (int k = lane; k < Hn; k += 32) {
        float xv = xrow[k];
        xr[(size_t)t * Hn + k] = to_tf32(xv);
#pragma unroll
        for (int e = 0; e < En; e++) acc[e] += xv * Wr[e * Hn + k];
    }
#pragma unroll
    for (int e = 0; e < En; e++) {
#pragma unroll
        for (int o = 16; o > 0; o >>= 1)
            acc[e] += __shfl_xor_sync(0xFFFFFFFFu, acc[e], o);
    }
    if (lane == 0) {
        int b0 = 0; float v0 = acc[0];
#pragma unroll
        for (int e = 1; e < En; e++) if (acc[e] > v0) { v0 = acc[e]; b0 = e; }
        int b1 = -1; float v1 = -1e30f;
#pragma unroll
        for (int e = 0; e < En; e++)
            if (e != b0 && acc[e] > v1) { v1 = acc[e]; b1 = e; }
        float w0 = 1.f / (1.f + expf(v1 - v0));
        float w1 = 1.f - w0;
        d_sel[t * 2 + 0] = b0; d_sel[t * 2 + 1] = b1;
        d_wgt[t * 2 + 0] = w0; d_wgt[t * 2 + 1] = w1;
        atomicAdd(&d_counts[b0], 1);
        atomicAdd(&d_counts[b1], 1);
#pragma unroll
        for (int e = 0; e < En; e++) logits_out[(size_t)t * En + e] = acc[e];
    }
}

__global__ void prefix_kernel() {
    if (threadIdx.x == 0) {
        int s = 0;
        for (int e = 0; e < En; e++) { d_offsets[e] = s; s += d_counts[e]; }
    }
}

__global__ void scatter_kernel() {
    int t = blockIdx.x * blockDim.x + threadIdx.x;
    if (t >= Tn) return;
#pragma unroll
    for (int k = 0; k < 2; k++) {
        int e = d_sel[t * 2 + k];
        int p = atomicAdd(&d_cursor[e], 1);
        int slot = d_offsets[e] + p;
        d_slot_token[slot] = t;
        d_token_slot[t * 2 + k] = slot;
    }
}

// g = tf32(silu(g) * u)
__global__ void silu_mul_kernel(float* __restrict__ g, const float* __restrict__ u,
                                size_t n4) {
    size_t idx = (size_t)blockIdx.x * blockDim.x + threadIdx.x;
    if (idx >= n4) return;
    size_t i = idx * 4;
    float4 gv = *reinterpret_cast<float4*>(g + i);
    float4 uv = *reinterpret_cast<const float4*>(u + i);
    gv.x = to_tf32(gv.x / (1.f + expf(-gv.x)) * uv.x);
    gv.y = to_tf32(gv.y / (1.f + expf(-gv.y)) * uv.y);
    gv.z = to_tf32(gv.z / (1.f + expf(-gv.z)) * uv.z);
    gv.w = to_tf32(gv.w / (1.f + expf(-gv.w)) * uv.w);
    *reinterpret_cast<float4*>(g + i) = gv;
}

__global__ void combine_kernel(float* __restrict__ out) {
    size_t idx = (size_t)blockIdx.x * blockDim.x + threadIdx.x;
    size_t i = idx * 4;
    if (i >= (size_t)Tn * Hn) return;
    int t = (int)(i / Hn);
    int h = (int)(i % Hn);
    int s0 = d_token_slot[t * 2 + 0];
    int s1 = d_token_slot[t * 2 + 1];
    float w0 = d_wgt[t * 2 + 0];
    float w1 = d_wgt[t * 2 + 1];
    float4 o = *reinterpret_cast<float4*>(out + i);
    float4 a = *reinterpret_cast<const float4*>(y2_buf + (size_t)s0 * Hn + h);
    float4 b = *reinterpret_cast<const float4*>(y2_buf + (size_t)s1 * Hn + h);
    o.x += w0 * a.x + w1 * b.x;
    o.y += w0 * a.y + w1 * b.y;
    o.z += w0 * a.z + w1 * b.z;
    o.w += w0 * a.w + w1 * b.w;
    *reinterpret_cast<float4*>(out + i) = o;
}

// ---------------- mma.sync tf32 GEMM: CTA 256x128, BK=32 ----------------
// C[M,N] = A[M,K] @ W[N,K]^T. 256 thr (8 warps, 2x4), warp tile 128x32.
// smem [row][k], stride 36 floats (conflict-free ldmatrix). 4-stage cp.async,
// single __syncthreads per chunk. Intensity 43.7 MAC/B (2x prior).
#define TSTR 36
#define AFL (256 * TSTR)          // floats in A tile
#define BFL (128 * TSTR)          // floats in B tile
#define STFL (AFL + BFL)          // 13824 floats per stage
#define NSTAGE 4

template <bool GATHER, bool EXPERT>
__global__ void __launch_bounds__(256, 1)
mma_gemm(const float* __restrict__ A, const float* __restrict__ W,
         float* __restrict__ C, int K, int ldC) {
    int rowBase = 0, segRows = Tn;
    const float* Wp = W;
    if (EXPERT) {
        int e = blockIdx.z;
        rowBase = d_offsets[e];
        segRows = d_counts[e];
        Wp = W + (size_t)e * ((size_t)ldC * K);
    }
    int byRow = blockIdx.y * 256;
    if (byRow >= segRows) return;
    int bx = blockIdx.x * 128;

    extern __shared__ float sm[];
    uint32_t sA = smem_u32(sm);
    const uint32_t STAGEB = (uint32_t)(STFL * 4);

    int tid = threadIdx.x;
    int lane = tid & 31, wid = tid >> 5;
    int gid = lane >> 2, tig = lane & 3;
    int wm = wid & 1, wn = wid >> 1;

    // ---- gmem->smem mapping: thread row (tid>>3)+r*32, q=(tid&7) float4 ----
    int lrow_ = tid >> 3;
    int q_ = tid & 7;
    uint32_t dstW = (uint32_t)((lrow_ * TSTR + q_ * 4) * 4);   // byte offset

    int arow[8];
#pragma unroll
    for (int r = 0; r < 8; r++) {
        int lrow = byRow + lrow_ + r * 32;
        int lcl = lrow < segRows ? lrow : (segRows - 1);
        arow[r] = GATHER ? d_slot_token[rowBase + lcl] : (rowBase + lcl);
    }
    const float* wB = Wp + (size_t)(bx + lrow_) * K + q_ * 4;

    // ---- ldmatrix lane addressing (byte offsets within a stage) ----
    int l7 = lane & 7;
    int l8 = lane & 8;
    uint32_t aOff[8];
#pragma unroll
    for (int mi = 0; mi < 8; mi++) {
        int rowA = wm * 128 + mi * 16 + l7 + l8;
        int colA = ((lane >> 4) & 1) * 4;
        aOff[mi] = (uint32_t)((rowA * TSTR + colA) * 4);
    }
    uint32_t bOff[4];
#pragma unroll
    for (int ni = 0; ni < 4; ni++) {
        int rowB = wn * 32 + ni * 8 + l7;
        int colB = ((lane >> 3) & 1) * 4;
        bOff[ni] = (uint32_t)((AFL + rowB * TSTR + colB) * 4);
    }

    float acc[8][4][4];
#pragma unroll
    for (int mi = 0; mi < 8; mi++)
#pragma unroll
        for (int ni = 0; ni < 4; ni++)
#pragma unroll
            for (int r = 0; r < 4; r++) acc[mi][ni][r] = 0.f;

    auto loadStage = [&](int j) {
        uint32_t st = sA + (uint32_t)(j % NSTAGE) * STAGEB;
        size_t koff = (size_t)j * 32;
#pragma unroll
        for (int r = 0; r < 8; r++)
            cpasync16(st + dstW + (uint32_t)(r * 32 * TSTR * 4),
                      A + (size_t)arow[r] * K + q_ * 4 + koff);
#pragma unroll
        for (int r = 0; r < 4; r++)
            cpasync16(st + (uint32_t)(AFL * 4) + dstW + (uint32_t)(r * 32 * TSTR * 4),
                      wB + (size_t)(r * 32) * K + koff);
        cpcommit();
    };

    int NKS = K / 32;
    loadStage(0);
    loadStage(1);
    loadStage(2);

    for (int i = 0; i < NKS; i++) {
        int rem = NKS - 1 - i;
        cpwait(rem > 2 ? 2 : rem);
        __syncthreads();
        if (i + 3 < NKS) loadStage(i + 3);

        uint32_t st = sA + (uint32_t)(i % NSTAGE) * STAGEB;
#pragma unroll
        for (int kk = 0; kk < 4; kk++) {
            uint32_t ko = (uint32_t)(kk * 32);    // 8 floats per kk
            uint32_t b[4][2];
#pragma unroll
            for (int ni = 0; ni < 4; ni++)
                ldsm_x2(b[ni], st + bOff[ni] + ko);
#pragma unroll
            for (int mi = 0; mi < 8; mi++) {
                uint32_t a[4];
                ldsm_x4(a, st + aOff[mi] + ko);
#pragma unroll
                for (int ni = 0; ni < 4; ni++)
                    mma8(acc[mi][ni], a, b[ni]);
            }
        }
    }

    // ---- epilogue ----
#pragma unroll
    for (int mi = 0; mi < 8; mi++) {
        int lr0 = byRow + wm * 128 + mi * 16 + gid;
#pragma unroll
        for (int half = 0; half < 2; half++) {
            int lr = lr0 + half * 8;
            if (lr < segRows) {
                float* cp = C + (size_t)(rowBase + lr) * ldC + bx + wn * 32 + 2 * tig;
#pragma unroll
                for (int ni = 0; ni < 4; ni++)
                    *reinterpret_cast<float2*>(cp + ni * 8) =
                        make_float2(acc[mi][ni][half * 2 + 0], acc[mi][ni][half * 2 + 1]);
            }
        }
    }
}

// ---------------- launch ----------------
extern "C" void kernel_launch(void* const* d_in, const int* in_sizes, int n_in,
                              void* d_out, int out_size) {
    const float* x    = (const float*)d_in[0];
    const float* Wg_s = (const float*)d_in[1];
    const float* Wu_s = (const float*)d_in[2];
    const float* Wd_s = (const float*)d_in[3];
    const float* Wg   = (const float*)d_in[4];
    const float* Wu   = (const float*)d_in[5];
    const float* Wd   = (const float*)d_in[6];
    const float* Wr   = (const float*)d_in[7];
    float* out = (float*)d_out;

    float *xr, *gsr, *usr, *dsr, *gr, *ur, *dr, *gp, *up, *g2p, *u2p, *y2p, *dlog;
    cudaGetSymbolAddress((void**)&xr,  xr_buf);
    cudaGetSymbolAddress((void**)&gsr, wgs_r);
    cudaGetSymbolAddress((void**)&usr, wus_r);
    cudaGetSymbolAddress((void**)&dsr, wds_r);
    cudaGetSymbolAddress((void**)&gr,  wg_r);
    cudaGetSymbolAddress((void**)&ur,  wu_r);
    cudaGetSymbolAddress((void**)&dr,  wd_r);
    cudaGetSymbolAddress((void**)&gp,  g_buf);
    cudaGetSymbolAddress((void**)&up,  u_buf);
    cudaGetSymbolAddress((void**)&g2p, g2_buf);
    cudaGetSymbolAddress((void**)&u2p, u2_buf);
    cudaGetSymbolAddress((void**)&y2p, y2_buf);
    cudaGetSymbolAddress((void**)&dlog, dummy_logits);

    bool has_logits = (out_size >= Tn * Hn + Tn * En);
    float* logits = has_logits ? (out + (size_t)Tn * Hn) : dlog;

    const int SMEM = NSTAGE * STFL * 4;   // 221184 B
    cudaFuncSetAttribute(mma_gemm<false, false>, cudaFuncAttributeMaxDynamicSharedMemorySize, SMEM);
    cudaFuncSetAttribute(mma_gemm<true,  true >, cudaFuncAttributeMaxDynamicSharedMemorySize, SMEM);
    cudaFuncSetAttribute(mma_gemm<false, true >, cudaFuncAttributeMaxDynamicSharedMemorySize, SMEM);

    // tf32 pre-rounding of weights (x rounded inside routing_kernel)
    auto roundN = [&](const float* s, float* d, size_t n) {
        size_t n4 = n / 4;
        round_kernel<<<(unsigned)((n4 + 255) / 256), 256>>>(s, d, n4);
    };
    roundN(Wg_s, gsr, (size_t)In * Hn);
    roundN(Wu_s, usr, (size_t)In * Hn);
    roundN(Wd_s, dsr, (size_t)Hn * In);
    roundN(Wg,   gr,  (size_t)En * In * Hn);
    roundN(Wu,   ur,  (size_t)En * In * Hn);
    roundN(Wd,   dr,  (size_t)En * Hn * In);

    // routing pipeline
    init_kernel<<<1, 32>>>();
    routing_kernel<<<Tn / 4, 128>>>(x, Wr, logits, xr);
    prefix_kernel<<<1, 32>>>();
    scatter_kernel<<<Tn / 256, 256>>>();

    // shared expert
    mma_gemm<false, false><<<dim3(In / 128, Tn / 256), 256, SMEM>>>(xr, gsr, gp, Hn, In);
    mma_gemm<false, false><<<dim3(In / 128, Tn / 256), 256, SMEM>>>(xr, usr, up, Hn, In);
    {
        size_t n4 = (size_t)Tn * In / 4;
        silu_mul_kernel<<<(unsigned)((n4 + 255) / 256), 256>>>(gp, up, n4);
    }
    mma_gemm<false, false><<<dim3(Hn / 128, Tn / 256), 256, SMEM>>>(gp, dsr, out, In, Hn);

    // MoE experts (gathered, compact slots; total slots = 2*Tn exactly)
    mma_gemm<true, true><<<dim3(In / 128, Tn / 256, En), 256, SMEM>>>(xr, gr, g2p, Hn, In);
    mma_gemm<true, true><<<dim3(In / 128, Tn / 256, En), 256, SMEM>>>(xr, ur, u2p, Hn, In);
    {
        size_t n4 = (size_t)2 * Tn * In / 4;
        silu_mul_kernel<<<(unsigned)((n4 + 255) / 256), 256>>>(g2p, u2p, n4);
    }
    mma_gemm<false, true><<<dim3(Hn / 128, Tn / 256, En), 256, SMEM>>>(g2p, dr, y2p, In, Hn);

    // final combine
    size_t n4c = (size_t)Tn * Hn / 4;
    combine_kernel<<<(unsigned)((n4c + 255) / 256), 256>>>(out);
}

// round 8
// speedup vs baseline: 1.6501x; 1.6501x over previous
#include <cuda_runtime.h>
#include <cuda_fp16.h>
#include <cstdint>
#include <math.h>

#define Tn 4096
#define Hn 1024
#define In 2816
#define En 7

// ---------------- static scratch ----------------
__device__ __half xh_buf[(size_t)Tn * Hn];
__device__ __half wgs_h[(size_t)In * Hn];
__device__ __half wus_h[(size_t)In * Hn];
__device__ __half wds_h[(size_t)Hn * In];
__device__ __half wg_h[(size_t)En * In * Hn];
__device__ __half wu_h[(size_t)En * In * Hn];
__device__ __half wd_h[(size_t)En * Hn * In];
__device__ __half h_buf[(size_t)Tn * In];
__device__ __half h2_buf[(size_t)2 * Tn * In];
__device__ float  y2_buf[(size_t)2 * Tn * Hn];
__device__ float  dummy_logits[(size_t)Tn * En];

__device__ int   d_counts[En];
__device__ int   d_offsets[En];
__device__ int   d_cursor[En];
__device__ int   d_sel[Tn * 2];
__device__ float d_wgt[Tn * 2];
__device__ int   d_slot_token[2 * Tn];
__device__ int   d_token_slot[Tn * 2];

// ---------------- PTX helpers (portable, sm_80+) ----------------
__device__ __forceinline__ uint32_t smem_u32(const void* p) {
    uint32_t a;
    asm("{ .reg .u64 t; cvta.to.shared.u64 t, %1; cvt.u32.u64 %0, t; }" : "=r"(a) : "l"(p));
    return a;
}
__device__ __forceinline__ void cpasync16(uint32_t dst, const void* src) {
    asm volatile("cp.async.cg.shared.global [%0], [%1], 16;" :: "r"(dst), "l"(src) : "memory");
}
__device__ __forceinline__ void cpcommit() {
    asm volatile("cp.async.commit_group;" ::: "memory");
}
__device__ __forceinline__ void cpwait(int n) {
    if (n <= 0)      asm volatile("cp.async.wait_group 0;" ::: "memory");
    else if (n == 1) asm volatile("cp.async.wait_group 1;" ::: "memory");
    else             asm volatile("cp.async.wait_group 2;" ::: "memory");
}
__device__ __forceinline__ void ldsm_x4(uint32_t* r, uint32_t addr) {
    asm volatile("ldmatrix.sync.aligned.m8n8.x4.shared.b16 {%0,%1,%2,%3}, [%4];"
        : "=r"(r[0]), "=r"(r[1]), "=r"(r[2]), "=r"(r[3]) : "r"(addr));
}
__device__ __forceinline__ void ldsm_x2(uint32_t* r, uint32_t addr) {
    asm volatile("ldmatrix.sync.aligned.m8n8.x2.shared.b16 {%0,%1}, [%2];"
        : "=r"(r[0]), "=r"(r[1]) : "r"(addr));
}
// D(16x8) += A(16x16) * B(16x8) ; fp16 operands, f32 accum
__device__ __forceinline__ void mma16(float* c, const uint32_t* a, const uint32_t* b) {
    asm volatile(
        "mma.sync.aligned.m16n8k16.row.col.f32.f16.f16.f32 "
        "{%0,%1,%2,%3}, {%4,%5,%6,%7}, {%8,%9}, {%0,%1,%2,%3};\n"
        : "+f"(c[0]), "+f"(c[1]), "+f"(c[2]), "+f"(c[3])
        : "r"(a[0]), "r"(a[1]), "r"(a[2]), "r"(a[3]),
          "r"(b[0]), "r"(b[1]));
}

// ---------------- small kernels ----------------
__global__ void init_kernel() {
    int i = threadIdx.x;
    if (i < En) { d_counts[i] = 0; d_cursor[i] = 0; }
}

// f32 -> f16 conversion (4 elements/thread, coalesced 8B stores)
__global__ void f2h_kernel(const float* __restrict__ s, __half* __restrict__ d, size_t n4) {
    size_t i = (size_t)blockIdx.x * blockDim.x + threadIdx.x;
    if (i >= n4) return;
    float4 v = reinterpret_cast<const float4*>(s)[i];
    __half2 h0 = __floats2half2_rn(v.x, v.y);
    __half2 h1 = __floats2half2_rn(v.z, v.w);
    uint2 pk;
    pk.x = *reinterpret_cast<uint32_t*>(&h0);
    pk.y = *reinterpret_cast<uint32_t*>(&h1);
    reinterpret_cast<uint2*>(d)[i] = pk;
}

__global__ void routing_kernel(const float* __restrict__ x,
                               const float* __restrict__ Wr,
                               float* __restrict__ logits_out,
                               __half* __restrict__ xh) {
    int warp = threadIdx.x >> 5;
    int lane = threadIdx.x & 31;
    int t = blockIdx.x * (blockDim.x >> 5) + warp;
    if (t >= Tn) return;
    const float* xrow = x + (size_t)t * Hn;
    float acc[En];
#pragma unroll
    for (int e = 0; e < En; e++) acc[e] = 0.f;
    for (int k = lane; k < Hn; k += 32) {
        float xv = xrow[k];
        xh[(size_t)t * Hn + k] = __float2half_rn(xv);
#pragma unroll
        for (int e = 0; e < En; e++) acc[e] += xv * Wr[e * Hn + k];
    }
#pragma unroll
    for (int e = 0; e < En; e++) {
#pragma unroll
        for (int o = 16; o > 0; o >>= 1)
            acc[e] += __shfl_xor_sync(0xFFFFFFFFu, acc[e], o);
    }
    if (lane == 0) {
        int b0 = 0; float v0 = acc[0];
#pragma unroll
        for (int e = 1; e < En; e++) if (acc[e] > v0) { v0 = acc[e]; b0 = e; }
        int b1 = -1; float v1 = -1e30f;
#pragma unroll
        for (int e = 0; e < En; e++)
            if (e != b0 && acc[e] > v1) { v1 = acc[e]; b1 = e; }
        float w0 = 1.f / (1.f + expf(v1 - v0));
        float w1 = 1.f - w0;
        d_sel[t * 2 + 0] = b0; d_sel[t * 2 + 1] = b1;
        d_wgt[t * 2 + 0] = w0; d_wgt[t * 2 + 1] = w1;
        atomicAdd(&d_counts[b0], 1);
        atomicAdd(&d_counts[b1], 1);
#pragma unroll
        for (int e = 0; e < En; e++) logits_out[(size_t)t * En + e] = acc[e];
    }
}

__global__ void prefix_kernel() {
    if (threadIdx.x == 0) {
        int s = 0;
        for (int e = 0; e < En; e++) { d_offsets[e] = s; s += d_counts[e]; }
    }
}

__global__ void scatter_kernel() {
    int t = blockIdx.x * blockDim.x + threadIdx.x;
    if (t >= Tn) return;
#pragma unroll
    for (int k = 0; k < 2; k++) {
        int e = d_sel[t * 2 + k];
        int p = atomicAdd(&d_cursor[e], 1);
        int slot = d_offsets[e] + p;
        d_slot_token[slot] = t;
        d_token_slot[t * 2 + k] = slot;
    }
}

__global__ void combine_kernel(float* __restrict__ out) {
    size_t idx = (size_t)blockIdx.x * blockDim.x + threadIdx.x;
    size_t i = idx * 4;
    if (i >= (size_t)Tn * Hn) return;
    int t = (int)(i / Hn);
    int h = (int)(i % Hn);
    int s0 = d_token_slot[t * 2 + 0];
    int s1 = d_token_slot[t * 2 + 1];
    float w0 = d_wgt[t * 2 + 0];
    float w1 = d_wgt[t * 2 + 1];
    float4 o = *reinterpret_cast<float4*>(out + i);
    float4 a = *reinterpret_cast<const float4*>(y2_buf + (size_t)s0 * Hn + h);
    float4 b = *reinterpret_cast<const float4*>(y2_buf + (size_t)s1 * Hn + h);
    o.x += w0 * a.x + w1 * b.x;
    o.y += w0 * a.y + w1 * b.y;
    o.z += w0 * a.z + w1 * b.z;
    o.w += w0 * a.w + w1 * b.w;
    *reinterpret_cast<float4*>(out + i) = o;
}

// ---------------- fp16 mma.sync GEMM (round-4 structure) ----------------
// C[M,N] = A[M,K] @ W[N,K]^T. CTA 128x128, BK=32 halves, 256 thr (8 warps),
// warp tile 64x32, mma m16n8k16, ldmatrix frags, 3-stage cp.async.
// smem [row][k] stride 40 halves (80B: conflict-free ldmatrix, rows hit
// banks 20r mod 32 = all distinct over 8 rows).
// FUSED: gate+up in one pass, epilogue writes h=silu(g)*u as fp16.
// GATHER: A row via d_slot_token. EXPERT: segment + per-expert W offset.
#define TSTR 40                    // halves per smem row
#define TILEB (128 * TSTR * 2)     // bytes per smem tile = 10240
#define NSTAGE 3

template <bool FUSED, bool GATHER, bool EXPERT>
__global__ void __launch_bounds__(256, 1)
mma_gemm(const __half* __restrict__ A, const __half* __restrict__ W0,
         const __half* __restrict__ W1, void* __restrict__ Cv, int K, int ldC) {
    int rowBase = 0, segRows = Tn;
    const __half* W0p = W0;
    const __half* W1p = W1;
    if (EXPERT) {
        int e = blockIdx.z;
        rowBase = d_offsets[e];
        segRows = d_counts[e];
        size_t ws = (size_t)ldC * K;
        W0p = W0 + (size_t)e * ws;
        if (FUSED) W1p = W1 + (size_t)e * ws;
    }
    int byRow = blockIdx.y * 128;
    if (byRow >= segRows) return;
    int bx = blockIdx.x * 128;

    extern __shared__ char sm[];
    uint32_t sA = smem_u32(sm);
    const int NOP = FUSED ? 3 : 2;
    const uint32_t STAGEB = (uint32_t)(NOP * TILEB);

    int tid = threadIdx.x;
    int lane = tid & 31, wid = tid >> 5;
    int gid = lane >> 2, tig = lane & 3;
    int wm = wid & 1, wn = wid >> 1;

    // ---- gmem->smem: c = it*256+tid; row=c>>2 (0..127), q=c&3 (16B=8 halves)
    int q_ = tid & 3;
    int row0 = tid >> 2;             // it=0 rows 0..63 ; it=1 rows 64..127
    uint32_t dstB[2];
    const __half* aP[2];
    const __half* w0P[2];
    const __half* w1P[2];
#pragma unroll
    for (int it = 0; it < 2; it++) {
        int row = row0 + it * 64;
        dstB[it] = (uint32_t)(row * TSTR * 2 + q_ * 16);
        int lrow = byRow + row;
        int lcl = lrow < segRows ? lrow : (segRows - 1);
        int arow = GATHER ? d_slot_token[rowBase + lcl] : (rowBase + lcl);
        aP[it]  = A   + (size_t)arow * K + q_ * 8;
        w0P[it] = W0p + (size_t)(bx + row) * K + q_ * 8;
        if (FUSED) w1P[it] = W1p + (size_t)(bx + row) * K + q_ * 8;
    }

    // ---- ldmatrix lane addressing (byte offsets within a stage) ----
    uint32_t aOff[4];
#pragma unroll
    for (int mi = 0; mi < 4; mi++) {
        int rowA = wm * 64 + mi * 16 + (lane & 15);
        int colA = ((lane >> 4) & 1) * 8;           // halves
        aOff[mi] = (uint32_t)((rowA * TSTR + colA) * 2);
    }
    uint32_t bOff[4];
#pragma unroll
    for (int ni = 0; ni < 4; ni++) {
        int rowB = wn * 32 + ni * 8 + (lane & 7);
        int colB = ((lane >> 3) & 1) * 8;           // halves
        bOff[ni] = (uint32_t)((rowB * TSTR + colB) * 2);
    }

    float acc0[4][4][4];
    float acc1[4][4][4];
#pragma unroll
    for (int mi = 0; mi < 4; mi++)
#pragma unroll
        for (int ni = 0; ni < 4; ni++)
#pragma unroll
            for (int r = 0; r < 4; r++) { acc0[mi][ni][r] = 0.f; if (FUSED) acc1[mi][ni][r] = 0.f; }

    auto loadStage = [&](int j) {
        uint32_t st = sA + (uint32_t)(j % NSTAGE) * STAGEB;
        size_t koff = (size_t)j * 32;   // halves
#pragma unroll
        for (int it = 0; it < 2; it++) {
            cpasync16(st + dstB[it], aP[it] + koff);
            cpasync16(st + (uint32_t)TILEB + dstB[it], w0P[it] + koff);
            if (FUSED)
                cpasync16(st + (uint32_t)(2 * TILEB) + dstB[it], w1P[it] + koff);
        }
        cpcommit();
    };

    int NKS = K / 32;
    loadStage(0);
    loadStage(1);

    for (int i = 0; i < NKS; i++) {
        if (i + 2 < NKS) loadStage(i + 2);
        int rem = NKS - 1 - i;
        cpwait(rem > 2 ? 2 : rem);
        __syncthreads();

        uint32_t stA = sA + (uint32_t)(i % NSTAGE) * STAGEB;
        uint32_t stB0 = stA + (uint32_t)TILEB;
        uint32_t stB1 = stA + (uint32_t)(2 * TILEB);

#pragma unroll
        for (int kk = 0; kk < 2; kk++) {
            uint32_t ko = (uint32_t)(kk * 32);      // 16 halves = 32 bytes
            uint32_t a[4][4];
#pragma unroll
            for (int mi = 0; mi < 4; mi++)
                ldsm_x4(a[mi], stA + aOff[mi] + ko);
            uint32_t b[4][2];
#pragma unroll
            for (int ni = 0; ni < 4; ni++)
                ldsm_x2(b[ni], stB0 + bOff[ni] + ko);
#pragma unroll
            for (int mi = 0; mi < 4; mi++)
#pragma unroll
                for (int ni = 0; ni < 4; ni++)
                    mma16(acc0[mi][ni], a[mi], b[ni]);
            if (FUSED) {
#pragma unroll
                for (int ni = 0; ni < 4; ni++)
                    ldsm_x2(b[ni], stB1 + bOff[ni] + ko);
#pragma unroll
                for (int mi = 0; mi < 4; mi++)
#pragma unroll
                    for (int ni = 0; ni < 4; ni++)
                        mma16(acc1[mi][ni], a[mi], b[ni]);
            }
        }
        __syncthreads();
    }

    // ---- epilogue ----
#pragma unroll
    for (int mi = 0; mi < 4; mi++) {
        int lr0 = byRow + wm * 64 + mi * 16 + gid;
#pragma unroll
        for (int half = 0; half < 2; half++) {
            int lr = lr0 + half * 8;
            if (lr >= segRows) continue;
            size_t cbase = (size_t)(rowBase + lr) * ldC + bx + wn * 32 + 2 * tig;
            if (FUSED) {
                __half* Ch = (__half*)Cv;
#pragma unroll
                for (int ni = 0; ni < 4; ni++) {
                    float g0 = acc0[mi][ni][half * 2 + 0];
                    float g1 = acc0[mi][ni][half * 2 + 1];
                    float u0 = acc1[mi][ni][half * 2 + 0];
                    float u1 = acc1[mi][ni][half * 2 + 1];
                    float h0 = g0 / (1.f + expf(-g0)) * u0;
                    float h1 = g1 / (1.f + expf(-g1)) * u1;
                    *reinterpret_cast<__half2*>(Ch + cbase + ni * 8) =
                        __floats2half2_rn(h0, h1);
                }
            } else {
                float* Cf = (float*)Cv;
#pragma unroll
                for (int ni = 0; ni < 4; ni++)
                    *reinterpret_cast<float2*>(Cf + cbase + ni * 8) =
                        make_float2(acc0[mi][ni][half * 2 + 0], acc0[mi][ni][half * 2 + 1]);
            }
        }
    }
}

// ---------------- launch ----------------
extern "C" void kernel_launch(void* const* d_in, const int* in_sizes, int n_in,
                              void* d_out, int out_size) {
    const float* x    = (const float*)d_in[0];
    const float* Wg_s = (const float*)d_in[1];
    const float* Wu_s = (const float*)d_in[2];
    const float* Wd_s = (const float*)d_in[3];
    const float* Wg   = (const float*)d_in[4];
    const float* Wu   = (const float*)d_in[5];
    const float* Wd   = (const float*)d_in[6];
    const float* Wr   = (const float*)d_in[7];
    float* out = (float*)d_out;

    __half *xh, *gsh, *ush, *dsh, *gh, *uh, *dh, *hp, *h2p;
    float *y2p, *dlog;
    cudaGetSymbolAddress((void**)&xh,  xh_buf);
    cudaGetSymbolAddress((void**)&gsh, wgs_h);
    cudaGetSymbolAddress((void**)&ush, wus_h);
    cudaGetSymbolAddress((void**)&dsh, wds_h);
    cudaGetSymbolAddress((void**)&gh,  wg_h);
    cudaGetSymbolAddress((void**)&uh,  wu_h);
    cudaGetSymbolAddress((void**)&dh,  wd_h);
    cudaGetSymbolAddress((void**)&hp,  h_buf);
    cudaGetSymbolAddress((void**)&h2p, h2_buf);
    cudaGetSymbolAddress((void**)&y2p, y2_buf);
    cudaGetSymbolAddress((void**)&dlog, dummy_logits);

    bool has_logits = (out_size >= Tn * Hn + Tn * En);
    float* logits = has_logits ? (out + (size_t)Tn * Hn) : dlog;

    const int SMF = NSTAGE * 3 * TILEB;   // 92160 B
    const int SMD = NSTAGE * 2 * TILEB;   // 61440 B
    cudaFuncSetAttribute(mma_gemm<true,  false, false>, cudaFuncAttributeMaxDynamicSharedMemorySize, SMF);
    cudaFuncSetAttribute(mma_gemm<true,  true,  true >, cudaFuncAttributeMaxDynamicSharedMemorySize, SMF);
    cudaFuncSetAttribute(mma_gemm<false, false, false>, cudaFuncAttributeMaxDynamicSharedMemorySize, SMD);
    cudaFuncSetAttribute(mma_gemm<false, false, true >, cudaFuncAttributeMaxDynamicSharedMemorySize, SMD);

    // f16 conversion of weights (x converted inside routing_kernel)
    auto convN = [&](const float* s, __half* d, size_t n) {
        size_t n4 = n / 4;
        f2h_kernel<<<(unsigned)((n4 + 255) / 256), 256>>>(s, d, n4);
    };
    convN(Wg_s, gsh, (size_t)In * Hn);
    convN(Wu_s, ush, (size_t)In * Hn);
    convN(Wd_s, dsh, (size_t)Hn * In);
    convN(Wg,   gh,  (size_t)En * In * Hn);
    convN(Wu,   uh,  (size_t)En * In * Hn);
    convN(Wd,   dh,  (size_t)En * Hn * In);

    // routing pipeline
    init_kernel<<<1, 32>>>();
    routing_kernel<<<Tn / 4, 128>>>(x, Wr, logits, xh);
    prefix_kernel<<<1, 32>>>();
    scatter_kernel<<<Tn / 256, 256>>>();

    // shared expert: fused gate+up -> h (fp16) ; down -> out (f32)
    mma_gemm<true, false, false><<<dim3(In / 128, Tn / 128), 256, SMF>>>(
        xh, gsh, ush, hp, Hn, In);
    mma_gemm<false, false, false><<<dim3(Hn / 128, Tn / 128), 256, SMD>>>(
        hp, dsh, nullptr, out, In, Hn);

    // MoE: fused gathered gate+up -> h2 (fp16) ; down -> y2 (f32, per slot)
    mma_gemm<true, true, true><<<dim3(In / 128, Tn / 128, En), 256, SMF>>>(
        xh, gh, uh, h2p, Hn, In);
    mma_gemm<false, false, true><<<dim3(Hn / 128, Tn / 128, En), 256, SMD>>>(
        h2p, dh, nullptr, y2p, In, Hn);

    // combine: out += w0*y2[s0] + w1*y2[s1]
    size_t n4c = (size_t)Tn * Hn / 4;
    combine_kernel<<<(unsigned)((n4c + 255) / 256), 256>>>(out);
}

// round 9
// speedup vs baseline: 2.1123x; 1.2801x over previous
#include <cuda_runtime.h>
#include <cuda_fp16.h>
#include <cstdint>
#include <math.h>

#define Tn 4096
#define Hn 1024
#define In 2816
#define En 7

// ---------------- static scratch ----------------
__device__ __half xh_buf[(size_t)Tn * Hn];
__device__ __half wgs_h[(size_t)In * Hn];
__device__ __half wus_h[(size_t)In * Hn];
__device__ __half wds_h[(size_t)Hn * In];
__device__ __half wg_h[(size_t)En * In * Hn];
__device__ __half wu_h[(size_t)En * In * Hn];
__device__ __half wd_h[(size_t)En * Hn * In];
__device__ __half h_buf[(size_t)Tn * In];
__device__ __half h2_buf[(size_t)2 * Tn * In];
__device__ float  y2_buf[(size_t)2 * Tn * Hn];
__device__ float  dummy_logits[(size_t)Tn * En];

__device__ int   d_counts[En];
__device__ int   d_offsets[En];
__device__ int   d_cursor[En];
__device__ int   d_sel[Tn * 2];
__device__ float d_wgt[Tn * 2];
__device__ int   d_slot_token[2 * Tn];
__device__ int   d_token_slot[Tn * 2];

// ---------------- PTX helpers (portable, sm_80+) ----------------
__device__ __forceinline__ uint32_t smem_u32(const void* p) {
    uint32_t a;
    asm("{ .reg .u64 t; cvta.to.shared.u64 t, %1; cvt.u32.u64 %0, t; }" : "=r"(a) : "l"(p));
    return a;
}
__device__ __forceinline__ void cpasync16(uint32_t dst, const void* src) {
    asm volatile("cp.async.cg.shared.global [%0], [%1], 16;" :: "r"(dst), "l"(src) : "memory");
}
__device__ __forceinline__ void cpcommit() {
    asm volatile("cp.async.commit_group;" ::: "memory");
}
__device__ __forceinline__ void cpwait(int n) {
    if (n <= 0)      asm volatile("cp.async.wait_group 0;" ::: "memory");
    else if (n == 1) asm volatile("cp.async.wait_group 1;" ::: "memory");
    else             asm volatile("cp.async.wait_group 2;" ::: "memory");
}
__device__ __forceinline__ void ldsm_x4(uint32_t* r, uint32_t addr) {
    asm volatile("ldmatrix.sync.aligned.m8n8.x4.shared.b16 {%0,%1,%2,%3}, [%4];"
        : "=r"(r[0]), "=r"(r[1]), "=r"(r[2]), "=r"(r[3]) : "r"(addr));
}
__device__ __forceinline__ void ldsm_x2(uint32_t* r, uint32_t addr) {
    asm volatile("ldmatrix.sync.aligned.m8n8.x2.shared.b16 {%0,%1}, [%2];"
        : "=r"(r[0]), "=r"(r[1]) : "r"(addr));
}
// D(16x8) += A(16x16) * B(16x8) ; fp16 operands, f32 accum
__device__ __forceinline__ void mma16(float* c, const uint32_t* a, const uint32_t* b) {
    asm volatile(
        "mma.sync.aligned.m16n8k16.row.col.f32.f16.f16.f32 "
        "{%0,%1,%2,%3}, {%4,%5,%6,%7}, {%8,%9}, {%0,%1,%2,%3};\n"
        : "+f"(c[0]), "+f"(c[1]), "+f"(c[2]), "+f"(c[3])
        : "r"(a[0]), "r"(a[1]), "r"(a[2]), "r"(a[3]),
          "r"(b[0]), "r"(b[1]));
}

// ---------------- small kernels ----------------
__global__ void init_kernel() {
    int i = threadIdx.x;
    if (i < En) { d_counts[i] = 0; d_cursor[i] = 0; }
}

__global__ void f2h_kernel(const float* __restrict__ s, __half* __restrict__ d, size_t n4) {
    size_t i = (size_t)blockIdx.x * blockDim.x + threadIdx.x;
    if (i >= n4) return;
    float4 v = reinterpret_cast<const float4*>(s)[i];
    __half2 h0 = __floats2half2_rn(v.x, v.y);
    __half2 h1 = __floats2half2_rn(v.z, v.w);
    uint2 pk;
    pk.x = *reinterpret_cast<uint32_t*>(&h0);
    pk.y = *reinterpret_cast<uint32_t*>(&h1);
    reinterpret_cast<uint2*>(d)[i] = pk;
}

__global__ void routing_kernel(const float* __restrict__ x,
                               const float* __restrict__ Wr,
                               float* __restrict__ logits_out,
                               __half* __restrict__ xh) {
    int warp = threadIdx.x >> 5;
    int lane = threadIdx.x & 31;
    int t = blockIdx.x * (blockDim.x >> 5) + warp;
    if (t >= Tn) return;
    const float* xrow = x + (size_t)t * Hn;
    float acc[En];
#pragma unroll
    for (int e = 0; e < En; e++) acc[e] = 0.f;
    for (int k = lane; k < Hn; k += 32) {
        float xv = xrow[k];
        xh[(size_t)t * Hn + k] = __float2half_rn(xv);
#pragma unroll
        for (int e = 0; e < En; e++) acc[e] += xv * Wr[e * Hn + k];
    }
#pragma unroll
    for (int e = 0; e < En; e++) {
#pragma unroll
        for (int o = 16; o > 0; o >>= 1)
            acc[e] += __shfl_xor_sync(0xFFFFFFFFu, acc[e], o);
    }
    if (lane == 0) {
        int b0 = 0; float v0 = acc[0];
#pragma unroll
        for (int e = 1; e < En; e++) if (acc[e] > v0) { v0 = acc[e]; b0 = e; }
        int b1 = -1; float v1 = -1e30f;
#pragma unroll
        for (int e = 0; e < En; e++)
            if (e != b0 && acc[e] > v1) { v1 = acc[e]; b1 = e; }
        float w0 = 1.f / (1.f + expf(v1 - v0));
        float w1 = 1.f - w0;
        d_sel[t * 2 + 0] = b0; d_sel[t * 2 + 1] = b1;
        d_wgt[t * 2 + 0] = w0; d_wgt[t * 2 + 1] = w1;
        atomicAdd(&d_counts[b0], 1);
        atomicAdd(&d_counts[b1], 1);
#pragma unroll
        for (int e = 0; e < En; e++) logits_out[(size_t)t * En + e] = acc[e];
    }
}

__global__ void prefix_kernel() {
    if (threadIdx.x == 0) {
        int s = 0;
        for (int e = 0; e < En; e++) { d_offsets[e] = s; s += d_counts[e]; }
    }
}

__global__ void scatter_kernel() {
    int t = blockIdx.x * blockDim.x + threadIdx.x;
    if (t >= Tn) return;
#pragma unroll
    for (int k = 0; k < 2; k++) {
        int e = d_sel[t * 2 + k];
        int p = atomicAdd(&d_cursor[e], 1);
        int slot = d_offsets[e] + p;
        d_slot_token[slot] = t;
        d_token_slot[t * 2 + k] = slot;
    }
}

__global__ void combine_kernel(float* __restrict__ out) {
    size_t idx = (size_t)blockIdx.x * blockDim.x + threadIdx.x;
    size_t i = idx * 4;
    if (i >= (size_t)Tn * Hn) return;
    int t = (int)(i / Hn);
    int h = (int)(i % Hn);
    int s0 = d_token_slot[t * 2 + 0];
    int s1 = d_token_slot[t * 2 + 1];
    float w0 = d_wgt[t * 2 + 0];
    float w1 = d_wgt[t * 2 + 1];
    float4 o = *reinterpret_cast<float4*>(out + i);
    float4 a = *reinterpret_cast<const float4*>(y2_buf + (size_t)s0 * Hn + h);
    float4 b = *reinterpret_cast<const float4*>(y2_buf + (size_t)s1 * Hn + h);
    o.x += w0 * a.x + w1 * b.x;
    o.y += w0 * a.y + w1 * b.y;
    o.z += w0 * a.z + w1 * b.z;
    o.w += w0 * a.w + w1 * b.w;
    *reinterpret_cast<float4*>(out + i) = o;
}

// ---------------- fp16 mma.sync GEMM: BK=64, 4-stage, 1 sync/chunk ----------
// C[M,N] = A[M,K] @ W[N,K]^T. CTA 128x128, BK=64 halves, 256 thr (8 warps),
// warp tile 64x32, mma m16n8k16, ldmatrix frags.
// smem [row][k], stride 72 halves (144B): ldmatrix banks 4r mod 32 distinct
// within each 8-row phase -> conflict-free.
// Pipeline: NSTAGE=4, prefetch AFTER compute (stage (i+3)%4=(i-1)%4, safe past
// barrier i), exactly one __syncthreads per chunk.
// FUSED: gate+up one pass, epilogue h=silu(g)*u in fp16.
// GATHER: A row via d_slot_token. EXPERT: segment + per-expert W offset.
#define TSTR 72                    // halves per smem row
#define TILEB (128 * TSTR * 2)     // 18432 B per tile
#define NSTAGE 4

template <bool FUSED, bool GATHER, bool EXPERT>
__global__ void __launch_bounds__(256, 1)
mma_gemm(const __half* __restrict__ A, const __half* __restrict__ W0,
         const __half* __restrict__ W1, void* __restrict__ Cv, int K, int ldC) {
    int rowBase = 0, segRows = Tn;
    const __half* W0p = W0;
    const __half* W1p = W1;
    if (EXPERT) {
        int e = blockIdx.z;
        rowBase = d_offsets[e];
        segRows = d_counts[e];
        size_t ws = (size_t)ldC * K;
        W0p = W0 + (size_t)e * ws;
        if (FUSED) W1p = W1 + (size_t)e * ws;
    }
    int byRow = blockIdx.y * 128;
    if (byRow >= segRows) return;
    int bx = blockIdx.x * 128;

    extern __shared__ char sm[];
    uint32_t sA = smem_u32(sm);
    const int NOP = FUSED ? 3 : 2;
    const uint32_t STAGEB = (uint32_t)(NOP * TILEB);

    int tid = threadIdx.x;
    int lane = tid & 31, wid = tid >> 5;
    int gid = lane >> 2, tig = lane & 3;
    int wm = wid & 1, wn = wid >> 1;

    // ---- gmem->smem: c = it*256+tid; row=c>>3 (0..127), q=c&7 (16B=8 halves)
    int q_ = tid & 7;
    int row0 = tid >> 3;             // rows row0 + it*32
    uint32_t dstB[4];
    const __half* aP[4];
    const __half* w0P[4];
    const __half* w1P[4];
#pragma unroll
    for (int it = 0; it < 4; it++) {
        int row = row0 + it * 32;
        dstB[it] = (uint32_t)(row * TSTR * 2 + q_ * 16);
        int lrow = byRow + row;
        int lcl = lrow < segRows ? lrow : (segRows - 1);
        int arow = GATHER ? d_slot_token[rowBase + lcl] : (rowBase + lcl);
        aP[it]  = A   + (size_t)arow * K + q_ * 8;
        w0P[it] = W0p + (size_t)(bx + row) * K + q_ * 8;
        if (FUSED) w1P[it] = W1p + (size_t)(bx + row) * K + q_ * 8;
    }

    // ---- ldmatrix lane addressing (byte offsets within a stage) ----
    uint32_t aOff[4];
#pragma unroll
    for (int mi = 0; mi < 4; mi++) {
        int rowA = wm * 64 + mi * 16 + (lane & 15);
        int colA = ((lane >> 4) & 1) * 8;           // halves
        aOff[mi] = (uint32_t)((rowA * TSTR + colA) * 2);
    }
    uint32_t bOff[4];
#pragma unroll
    for (int ni = 0; ni < 4; ni++) {
        int rowB = wn * 32 + ni * 8 + (lane & 7);
        int colB = ((lane >> 3) & 1) * 8;           // halves
        bOff[ni] = (uint32_t)((rowB * TSTR + colB) * 2);
    }

    float acc0[4][4][4];
    float acc1[4][4][4];
#pragma unroll
    for (int mi = 0; mi < 4; mi++)
#pragma unroll
        for (int ni = 0; ni < 4; ni++)
#pragma unroll
            for (int r = 0; r < 4; r++) { acc0[mi][ni][r] = 0.f; if (FUSED) acc1[mi][ni][r] = 0.f; }

    auto loadStage = [&](int j) {
        uint32_t st = sA + (uint32_t)(j % NSTAGE) * STAGEB;
        size_t koff = (size_t)j * 64;   // halves
#pragma unroll
        for (int it = 0; it < 4; it++)
            cpasync16(st + dstB[it], aP[it] + koff);
#pragma unroll
        for (int it = 0; it < 4; it++)
            cpasync16(st + (uint32_t)TILEB + dstB[it], w0P[it] + koff);
        if (FUSED) {
#pragma unroll
            for (int it = 0; it < 4; it++)
                cpasync16(st + (uint32_t)(2 * TILEB) + dstB[it], w1P[it] + koff);
        }
        cpcommit();
    };

    int NKS = K / 64;
    loadStage(0);
    loadStage(1);
    loadStage(2);

    for (int i = 0; i < NKS; i++) {
        int rem = NKS - 1 - i;
        cpwait(rem > 2 ? 2 : rem);
        __syncthreads();

        uint32_t stA = sA + (uint32_t)(i % NSTAGE) * STAGEB;
        uint32_t stB0 = stA + (uint32_t)TILEB;
        uint32_t stB1 = stA + (uint32_t)(2 * TILEB);

#pragma unroll
        for (int kk = 0; kk < 4; kk++) {
            uint32_t ko = (uint32_t)(kk * 32);      // 16 halves = 32 bytes
            uint32_t a[4][4];
#pragma unroll
            for (int mi = 0; mi < 4; mi++)
                ldsm_x4(a[mi], stA + aOff[mi] + ko);
            uint32_t b[4][2];
#pragma unroll
            for (int ni = 0; ni < 4; ni++)
                ldsm_x2(b[ni], stB0 + bOff[ni] + ko);
#pragma unroll
            for (int mi = 0; mi < 4; mi++)
#pragma unroll
                for (int ni = 0; ni < 4; ni++)
                    mma16(acc0[mi][ni], a[mi], b[ni]);
            if (FUSED) {
#pragma unroll
                for (int ni = 0; ni < 4; ni++)
                    ldsm_x2(b[ni], stB1 + bOff[ni] + ko);
#pragma unroll
                for (int mi = 0; mi < 4; mi++)
#pragma unroll
                    for (int ni = 0; ni < 4; ni++)
                        mma16(acc1[mi][ni], a[mi], b[ni]);
            }
        }
        // prefetch AFTER compute: writes stage (i-1)%4, safe (barrier i passed)
        if (i + 3 < NKS) loadStage(i + 3);
    }

    // ---- epilogue ----
#pragma unroll
    for (int mi = 0; mi < 4; mi++) {
        int lr0 = byRow + wm * 64 + mi * 16 + gid;
#pragma unroll
        for (int half = 0; half < 2; half++) {
            int lr = lr0 + half * 8;
            if (lr >= segRows) continue;
            size_t cbase = (size_t)(rowBase + lr) * ldC + bx + wn * 32 + 2 * tig;
            if (FUSED) {
                __half* Ch = (__half*)Cv;
#pragma unroll
                for (int ni = 0; ni < 4; ni++) {
                    float g0 = acc0[mi][ni][half * 2 + 0];
                    float g1 = acc0[mi][ni][half * 2 + 1];
                    float u0 = acc1[mi][ni][half * 2 + 0];
                    float u1 = acc1[mi][ni][half * 2 + 1];
                    float h0 = g0 / (1.f + expf(-g0)) * u0;
                    float h1 = g1 / (1.f + expf(-g1)) * u1;
                    *reinterpret_cast<__half2*>(Ch + cbase + ni * 8) =
                        __floats2half2_rn(h0, h1);
                }
            } else {
                float* Cf = (float*)Cv;
#pragma unroll
                for (int ni = 0; ni < 4; ni++)
                    *reinterpret_cast<float2*>(Cf + cbase + ni * 8) =
                        make_float2(acc0[mi][ni][half * 2 + 0], acc0[mi][ni][half * 2 + 1]);
            }
        }
    }
}

// ---------------- launch ----------------
extern "C" void kernel_launch(void* const* d_in, const int* in_sizes, int n_in,
                              void* d_out, int out_size) {
    const float* x    = (const float*)d_in[0];
    const float* Wg_s = (const float*)d_in[1];
    const float* Wu_s = (const float*)d_in[2];
    const float* Wd_s = (const float*)d_in[3];
    const float* Wg   = (const float*)d_in[4];
    const float* Wu   = (const float*)d_in[5];
    const float* Wd   = (const float*)d_in[6];
    const float* Wr   = (const float*)d_in[7];
    float* out = (float*)d_out;

    __half *xh, *gsh, *ush, *dsh, *gh, *uh, *dh, *hp, *h2p;
    float *y2p, *dlog;
    cudaGetSymbolAddress((void**)&xh,  xh_buf);
    cudaGetSymbolAddress((void**)&gsh, wgs_h);
    cudaGetSymbolAddress((void**)&ush, wus_h);
    cudaGetSymbolAddress((void**)&dsh, wds_h);
    cudaGetSymbolAddress((void**)&gh,  wg_h);
    cudaGetSymbolAddress((void**)&uh,  wu_h);
    cudaGetSymbolAddress((void**)&dh,  wd_h);
    cudaGetSymbolAddress((void**)&hp,  h_buf);
    cudaGetSymbolAddress((void**)&h2p, h2_buf);
    cudaGetSymbolAddress((void**)&y2p, y2_buf);
    cudaGetSymbolAddress((void**)&dlog, dummy_logits);

    bool has_logits = (out_size >= Tn * Hn + Tn * En);
    float* logits = has_logits ? (out + (size_t)Tn * Hn) : dlog;

    const int SMF = NSTAGE * 3 * TILEB;   // 221184 B
    const int SMD = NSTAGE * 2 * TILEB;   // 147456 B
    cudaFuncSetAttribute(mma_gemm<true,  false, false>, cudaFuncAttributeMaxDynamicSharedMemorySize, SMF);
    cudaFuncSetAttribute(mma_gemm<true,  true,  true >, cudaFuncAttributeMaxDynamicSharedMemorySize, SMF);
    cudaFuncSetAttribute(mma_gemm<false, false, false>, cudaFuncAttributeMaxDynamicSharedMemorySize, SMD);
    cudaFuncSetAttribute(mma_gemm<false, false, true >, cudaFuncAttributeMaxDynamicSharedMemorySize, SMD);

    // f16 conversion of weights (x converted inside routing_kernel)
    auto convN = [&](const float* s, __half* d, size_t n) {
        size_t n4 = n / 4;
        f2h_kernel<<<(unsigned)((n4 + 255) / 256), 256>>>(s, d, n4);
    };
    convN(Wg_s, gsh, (size_t)In * Hn);
    convN(Wu_s, ush, (size_t)In * Hn);
    convN(Wd_s, dsh, (size_t)Hn * In);
    convN(Wg,   gh,  (size_t)En * In * Hn);
    convN(Wu,   uh,  (size_t)En * In * Hn);
    convN(Wd,   dh,  (size_t)En * Hn * In);

    // routing pipeline
    init_kernel<<<1, 32>>>();
    routing_kernel<<<Tn / 4, 128>>>(x, Wr, logits, xh);
    prefix_kernel<<<1, 32>>>();
    scatter_kernel<<<Tn / 256, 256>>>();

    // shared expert: fused gate+up -> h (fp16) ; down -> out (f32)
    mma_gemm<true, false, false><<<dim3(In / 128, Tn / 128), 256, SMF>>>(
        xh, gsh, ush, hp, Hn, In);
    mma_gemm<false, false, false><<<dim3(Hn / 128, Tn / 128), 256, SMD>>>(
        hp, dsh, nullptr, out, In, Hn);

    // MoE: fused gathered gate+up -> h2 (fp16) ; down -> y2 (f32, per slot)
    mma_gemm<true, true, true><<<dim3(In / 128, Tn / 128, En), 256, SMF>>>(
        xh, gh, uh, h2p, Hn, In);
    mma_gemm<false, false, true><<<dim3(Hn / 128, Tn / 128, En), 256, SMD>>>(
        h2p, dh, nullptr, y2p, In, Hn);

    // combine: out += w0*y2[s0] + w1*y2[s1]
    size_t n4c = (size_t)Tn * Hn / 4;
    combine_kernel<<<(unsigned)((n4c + 255) / 256), 256>>>(out);
}

// round 10
// speedup vs baseline: 2.1239x; 1.0055x over previous
#include <cuda_runtime.h>
#include <cuda_fp16.h>
#include <cstdint>
#include <math.h>

#define Tn 4096
#define Hn 1024
#define In 2816
#define En 7

// ---------------- static scratch ----------------
__device__ __half xh_buf[(size_t)Tn * Hn];
__device__ __half wgs_h[(size_t)In * Hn];
__device__ __half wus_h[(size_t)In * Hn];
__device__ __half wds_h[(size_t)Hn * In];
__device__ __half wg_h[(size_t)En * In * Hn];
__device__ __half wu_h[(size_t)En * In * Hn];
__device__ __half wd_h[(size_t)En * Hn * In];
__device__ __half h_buf[(size_t)Tn * In];
__device__ __half h2_buf[(size_t)2 * Tn * In];
__device__ float  y2_buf[(size_t)2 * Tn * Hn];
__device__ float  dummy_logits[(size_t)Tn * En];

__device__ int   d_counts[En];
__device__ int   d_offsets[En];
__device__ int   d_cursor[En];
__device__ int   d_sel[Tn * 2];
__device__ float d_wgt[Tn * 2];
__device__ int   d_slot_token[2 * Tn];
__device__ int   d_token_slot[Tn * 2];

// ---------------- side stream for prologue overlap (created at load time;
// streams/events are not device-memory allocations) ----------------
struct SideStream {
    cudaStream_t s2;
    cudaEvent_t  evFork, evJoin;
    SideStream() {
        cudaStreamCreateWithFlags(&s2, cudaStreamNonBlocking);
        cudaEventCreateWithFlags(&evFork, cudaEventDisableTiming);
        cudaEventCreateWithFlags(&evJoin, cudaEventDisableTiming);
    }
};
static SideStream g_ss;

// ---------------- PTX helpers (portable, sm_80+) ----------------
__device__ __forceinline__ uint32_t smem_u32(const void* p) {
    uint32_t a;
    asm("{ .reg .u64 t; cvta.to.shared.u64 t, %1; cvt.u32.u64 %0, t; }" : "=r"(a) : "l"(p));
    return a;
}
__device__ __forceinline__ void cpasync16(uint32_t dst, const void* src) {
    asm volatile("cp.async.cg.shared.global [%0], [%1], 16;" :: "r"(dst), "l"(src) : "memory");
}
__device__ __forceinline__ void cpcommit() {
    asm volatile("cp.async.commit_group;" ::: "memory");
}
__device__ __forceinline__ void cpwait(int n) {
    if (n <= 0)      asm volatile("cp.async.wait_group 0;" ::: "memory");
    else if (n == 1) asm volatile("cp.async.wait_group 1;" ::: "memory");
    else             asm volatile("cp.async.wait_group 2;" ::: "memory");
}
__device__ __forceinline__ void ldsm_x4(uint32_t* r, uint32_t addr) {
    asm volatile("ldmatrix.sync.aligned.m8n8.x4.shared.b16 {%0,%1,%2,%3}, [%4];"
        : "=r"(r[0]), "=r"(r[1]), "=r"(r[2]), "=r"(r[3]) : "r"(addr));
}
__device__ __forceinline__ void ldsm_x2(uint32_t* r, uint32_t addr) {
    asm volatile("ldmatrix.sync.aligned.m8n8.x2.shared.b16 {%0,%1}, [%2];"
        : "=r"(r[0]), "=r"(r[1]) : "r"(addr));
}
// D(16x8) += A(16x16) * B(16x8) ; fp16 operands, f32 accum
__device__ __forceinline__ void mma16(float* c, const uint32_t* a, const uint32_t* b) {
    asm volatile(
        "mma.sync.aligned.m16n8k16.row.col.f32.f16.f16.f32 "
        "{%0,%1,%2,%3}, {%4,%5,%6,%7}, {%8,%9}, {%0,%1,%2,%3};\n"
        : "+f"(c[0]), "+f"(c[1]), "+f"(c[2]), "+f"(c[3])
        : "r"(a[0]), "r"(a[1]), "r"(a[2]), "r"(a[3]),
          "r"(b[0]), "r"(b[1]));
}

// ---------------- small kernels ----------------
__global__ void init_kernel() {
    int i = threadIdx.x;
    if (i < En) { d_counts[i] = 0; d_cursor[i] = 0; }
}

__global__ void f2h_kernel(const float* __restrict__ s, __half* __restrict__ d, size_t n4) {
    size_t i = (size_t)blockIdx.x * blockDim.x + threadIdx.x;
    if (i >= n4) return;
    float4 v = reinterpret_cast<const float4*>(s)[i];
    __half2 h0 = __floats2half2_rn(v.x, v.y);
    __half2 h1 = __floats2half2_rn(v.z, v.w);
    uint2 pk;
    pk.x = *reinterpret_cast<uint32_t*>(&h0);
    pk.y = *reinterpret_cast<uint32_t*>(&h1);
    reinterpret_cast<uint2*>(d)[i] = pk;
}

__global__ void routing_kernel(const float* __restrict__ x,
                               const float* __restrict__ Wr,
                               float* __restrict__ logits_out,
                               __half* __restrict__ xh) {
    int warp = threadIdx.x >> 5;
    int lane = threadIdx.x & 31;
    int t = blockIdx.x * (blockDim.x >> 5) + warp;
    if (t >= Tn) return;
    const float* xrow = x + (size_t)t * Hn;
    float acc[En];
#pragma unroll
    for (int e = 0; e < En; e++) acc[e] = 0.f;
    for (int k = lane; k < Hn; k += 32) {
        float xv = xrow[k];
        xh[(size_t)t * Hn + k] = __float2half_rn(xv);
#pragma unroll
        for (int e = 0; e < En; e++) acc[e] += xv * Wr[e * Hn + k];
    }
#pragma unroll
    for (int e = 0; e < En; e++) {
#pragma unroll
        for (int o = 16; o > 0; o >>= 1)
            acc[e] += __shfl_xor_sync(0xFFFFFFFFu, acc[e], o);
    }
    if (lane == 0) {
        int b0 = 0; float v0 = acc[0];
#pragma unroll
        for (int e = 1; e < En; e++) if (acc[e] > v0) { v0 = acc[e]; b0 = e; }
        int b1 = -1; float v1 = -1e30f;
#pragma unroll
        for (int e = 0; e < En; e++)
            if (e != b0 && acc[e] > v1) { v1 = acc[e]; b1 = e; }
        float w0 = 1.f / (1.f + expf(v1 - v0));
        float w1 = 1.f - w0;
        d_sel[t * 2 + 0] = b0; d_sel[t * 2 + 1] = b1;
        d_wgt[t * 2 + 0] = w0; d_wgt[t * 2 + 1] = w1;
        atomicAdd(&d_counts[b0], 1);
        atomicAdd(&d_counts[b1], 1);
#pragma unroll
        for (int e = 0; e < En; e++) logits_out[(size_t)t * En + e] = acc[e];
    }
}

__global__ void prefix_kernel() {
    if (threadIdx.x == 0) {
        int s = 0;
        for (int e = 0; e < En; e++) { d_offsets[e] = s; s += d_counts[e]; }
    }
}

__global__ void scatter_kernel() {
    int t = blockIdx.x * blockDim.x + threadIdx.x;
    if (t >= Tn) return;
#pragma unroll
    for (int k = 0; k < 2; k++) {
        int e = d_sel[t * 2 + k];
        int p = atomicAdd(&d_cursor[e], 1);
        int slot = d_offsets[e] + p;
        d_slot_token[slot] = t;
        d_token_slot[t * 2 + k] = slot;
    }
}

__global__ void combine_kernel(float* __restrict__ out) {
    size_t idx = (size_t)blockIdx.x * blockDim.x + threadIdx.x;
    size_t i = idx * 4;
    if (i >= (size_t)Tn * Hn) return;
    int t = (int)(i / Hn);
    int h = (int)(i % Hn);
    int s0 = d_token_slot[t * 2 + 0];
    int s1 = d_token_slot[t * 2 + 1];
    float w0 = d_wgt[t * 2 + 0];
    float w1 = d_wgt[t * 2 + 1];
    float4 o = *reinterpret_cast<float4*>(out + i);
    float4 a = *reinterpret_cast<const float4*>(y2_buf + (size_t)s0 * Hn + h);
    float4 b = *reinterpret_cast<const float4*>(y2_buf + (size_t)s1 * Hn + h);
    o.x += w0 * a.x + w1 * b.x;
    o.y += w0 * a.y + w1 * b.y;
    o.z += w0 * a.z + w1 * b.z;
    o.w += w0 * a.w + w1 * b.w;
    *reinterpret_cast<float4*>(out + i) = o;
}

// ---------------- fp16 mma.sync GEMM: BK=64, 4-stage, 1 sync/chunk ----------
// (unchanged from round-8 winner)
#define TSTR 72                    // halves per smem row
#define TILEB (128 * TSTR * 2)     // 18432 B per tile
#define NSTAGE 4

template <bool FUSED, bool GATHER, bool EXPERT>
__global__ void __launch_bounds__(256, 1)
mma_gemm(const __half* __restrict__ A, const __half* __restrict__ W0,
         const __half* __restrict__ W1, void* __restrict__ Cv, int K, int ldC) {
    int rowBase = 0, segRows = Tn;
    const __half* W0p = W0;
    const __half* W1p = W1;
    if (EXPERT) {
        int e = blockIdx.z;
        rowBase = d_offsets[e];
        segRows = d_counts[e];
        size_t ws = (size_t)ldC * K;
        W0p = W0 + (size_t)e * ws;
        if (FUSED) W1p = W1 + (size_t)e * ws;
    }
    int byRow = blockIdx.y * 128;
    if (byRow >= segRows) return;
    int bx = blockIdx.x * 128;

    extern __shared__ char sm[];
    uint32_t sA = smem_u32(sm);
    const int NOP = FUSED ? 3 : 2;
    const uint32_t STAGEB = (uint32_t)(NOP * TILEB);

    int tid = threadIdx.x;
    int lane = tid & 31, wid = tid >> 5;
    int gid = lane >> 2, tig = lane & 3;
    int wm = wid & 1, wn = wid >> 1;

    int q_ = tid & 7;
    int row0 = tid >> 3;
    uint32_t dstB[4];
    const __half* aP[4];
    const __half* w0P[4];
    const __half* w1P[4];
#pragma unroll
    for (int it = 0; it < 4; it++) {
        int row = row0 + it * 32;
        dstB[it] = (uint32_t)(row * TSTR * 2 + q_ * 16);
        int lrow = byRow + row;
        int lcl = lrow < segRows ? lrow : (segRows - 1);
        int arow = GATHER ? d_slot_token[rowBase + lcl] : (rowBase + lcl);
        aP[it]  = A   + (size_t)arow * K + q_ * 8;
        w0P[it] = W0p + (size_t)(bx + row) * K + q_ * 8;
        if (FUSED) w1P[it] = W1p + (size_t)(bx + row) * K + q_ * 8;
    }

    uint32_t aOff[4];
#pragma unroll
    for (int mi = 0; mi < 4; mi++) {
        int rowA = wm * 64 + mi * 16 + (lane & 15);
        int colA = ((lane >> 4) & 1) * 8;
        aOff[mi] = (uint32_t)((rowA * TSTR + colA) * 2);
    }
    uint32_t bOff[4];
#pragma unroll
    for (int ni = 0; ni < 4; ni++) {
        int rowB = wn * 32 + ni * 8 + (lane & 7);
        int colB = ((lane >> 3) & 1) * 8;
        bOff[ni] = (uint32_t)((rowB * TSTR + colB) * 2);
    }

    float acc0[4][4][4];
    float acc1[4][4][4];
#pragma unroll
    for (int mi = 0; mi < 4; mi++)
#pragma unroll
        for (int ni = 0; ni < 4; ni++)
#pragma unroll
            for (int r = 0; r < 4; r++) { acc0[mi][ni][r] = 0.f; if (FUSED) acc1[mi][ni][r] = 0.f; }

    auto loadStage = [&](int j) {
        uint32_t st = sA + (uint32_t)(j % NSTAGE) * STAGEB;
        size_t koff = (size_t)j * 64;
#pragma unroll
        for (int it = 0; it < 4; it++)
            cpasync16(st + dstB[it], aP[it] + koff);
#pragma unroll
        for (int it = 0; it < 4; it++)
            cpasync16(st + (uint32_t)TILEB + dstB[it], w0P[it] + koff);
        if (FUSED) {
#pragma unroll
            for (int it = 0; it < 4; it++)
                cpasync16(st + (uint32_t)(2 * TILEB) + dstB[it], w1P[it] + koff);
        }
        cpcommit();
    };

    int NKS = K / 64;
    loadStage(0);
    loadStage(1);
    loadStage(2);

    for (int i = 0; i < NKS; i++) {
        int rem = NKS - 1 - i;
        cpwait(rem > 2 ? 2 : rem);
        __syncthreads();

        uint32_t stA = sA + (uint32_t)(i % NSTAGE) * STAGEB;
        uint32_t stB0 = stA + (uint32_t)TILEB;
        uint32_t stB1 = stA + (uint32_t)(2 * TILEB);

#pragma unroll
        for (int kk = 0; kk < 4; kk++) {
            uint32_t ko = (uint32_t)(kk * 32);
            uint32_t a[4][4];
#pragma unroll
            for (int mi = 0; mi < 4; mi++)
                ldsm_x4(a[mi], stA + aOff[mi] + ko);
            uint32_t b[4][2];
#pragma unroll
            for (int ni = 0; ni < 4; ni++)
                ldsm_x2(b[ni], stB0 + bOff[ni] + ko);
#pragma unroll
            for (int mi = 0; mi < 4; mi++)
#pragma unroll
                for (int ni = 0; ni < 4; ni++)
                    mma16(acc0[mi][ni], a[mi], b[ni]);
            if (FUSED) {
#pragma unroll
                for (int ni = 0; ni < 4; ni++)
                    ldsm_x2(b[ni], stB1 + bOff[ni] + ko);
#pragma unroll
                for (int mi = 0; mi < 4; mi++)
#pragma unroll
                    for (int ni = 0; ni < 4; ni++)
                        mma16(acc1[mi][ni], a[mi], b[ni]);
            }
        }
        if (i + 3 < NKS) loadStage(i + 3);
    }

    // ---- epilogue ----
#pragma unroll
    for (int mi = 0; mi < 4; mi++) {
        int lr0 = byRow + wm * 64 + mi * 16 + gid;
#pragma unroll
        for (int half = 0; half < 2; half++) {
            int lr = lr0 + half * 8;
            if (lr >= segRows) continue;
            size_t cbase = (size_t)(rowBase + lr) * ldC + bx + wn * 32 + 2 * tig;
            if (FUSED) {
                __half* Ch = (__half*)Cv;
#pragma unroll
                for (int ni = 0; ni < 4; ni++) {
                    float g0 = acc0[mi][ni][half * 2 + 0];
                    float g1 = acc0[mi][ni][half * 2 + 1];
                    float u0 = acc1[mi][ni][half * 2 + 0];
                    float u1 = acc1[mi][ni][half * 2 + 1];
                    float h0 = g0 / (1.f + expf(-g0)) * u0;
                    float h1 = g1 / (1.f + expf(-g1)) * u1;
                    *reinterpret_cast<__half2*>(Ch + cbase + ni * 8) =
                        __floats2half2_rn(h0, h1);
                }
            } else {
                float* Cf = (float*)Cv;
#pragma unroll
                for (int ni = 0; ni < 4; ni++)
                    *reinterpret_cast<float2*>(Cf + cbase + ni * 8) =
                        make_float2(acc0[mi][ni][half * 2 + 0], acc0[mi][ni][half * 2 + 1]);
            }
        }
    }
}

// ---------------- launch ----------------
extern "C" void kernel_launch(void* const* d_in, const int* in_sizes, int n_in,
                              void* d_out, int out_size) {
    const float* x    = (const float*)d_in[0];
    const float* Wg_s = (const float*)d_in[1];
    const float* Wu_s = (const float*)d_in[2];
    const float* Wd_s = (const float*)d_in[3];
    const float* Wg   = (const float*)d_in[4];
    const float* Wu   = (const float*)d_in[5];
    const float* Wd   = (const float*)d_in[6];
    const float* Wr   = (const float*)d_in[7];
    float* out = (float*)d_out;

    __half *xh, *gsh, *ush, *dsh, *gh, *uh, *dh, *hp, *h2p;
    float *y2p, *dlog;
    cudaGetSymbolAddress((void**)&xh,  xh_buf);
    cudaGetSymbolAddress((void**)&gsh, wgs_h);
    cudaGetSymbolAddress((void**)&ush, wus_h);
    cudaGetSymbolAddress((void**)&dsh, wds_h);
    cudaGetSymbolAddress((void**)&gh,  wg_h);
    cudaGetSymbolAddress((void**)&uh,  wu_h);
    cudaGetSymbolAddress((void**)&dh,  wd_h);
    cudaGetSymbolAddress((void**)&hp,  h_buf);
    cudaGetSymbolAddress((void**)&h2p, h2_buf);
    cudaGetSymbolAddress((void**)&y2p, y2_buf);
    cudaGetSymbolAddress((void**)&dlog, dummy_logits);

    bool has_logits = (out_size >= Tn * Hn + Tn * En);
    float* logits = has_logits ? (out + (size_t)Tn * Hn) : dlog;

    const int SMF = NSTAGE * 3 * TILEB;   // 221184 B
    const int SMD = NSTAGE * 2 * TILEB;   // 147456 B
    cudaFuncSetAttribute(mma_gemm<true,  false, false>, cudaFuncAttributeMaxDynamicSharedMemorySize, SMF);
    cudaFuncSetAttribute(mma_gemm<true,  true,  true >, cudaFuncAttributeMaxDynamicSharedMemorySize, SMF);
    cudaFuncSetAttribute(mma_gemm<false, false, false>, cudaFuncAttributeMaxDynamicSharedMemorySize, SMD);
    cudaFuncSetAttribute(mma_gemm<false, false, true >, cudaFuncAttributeMaxDynamicSharedMemorySize, SMD);

    auto convN = [&](const float* s, __half* d, size_t n, cudaStream_t st) {
        size_t n4 = n / 4;
        f2h_kernel<<<(unsigned)((n4 + 255) / 256), 256, 0, st>>>(s, d, n4);
    };

    // ---- fork: MoE weight conversion (~55us HBM) on side stream, hidden
    // behind routing + shared-expert GEMMs on the main stream ----
    cudaEventRecord(g_ss.evFork, 0);
    cudaStreamWaitEvent(g_ss.s2, g_ss.evFork, 0);
    convN(Wg, gh, (size_t)En * In * Hn, g_ss.s2);
    convN(Wu, uh, (size_t)En * In * Hn, g_ss.s2);
    convN(Wd, dh, (size_t)En * Hn * In, g_ss.s2);
    cudaEventRecord(g_ss.evJoin, g_ss.s2);

    // main stream: shared weights (cheap) + routing pipeline
    convN(Wg_s, gsh, (size_t)In * Hn, 0);
    convN(Wu_s, ush, (size_t)In * Hn, 0);
    convN(Wd_s, dsh, (size_t)Hn * In, 0);
    init_kernel<<<1, 32>>>();
    routing_kernel<<<Tn / 4, 128>>>(x, Wr, logits, xh);
    prefix_kernel<<<1, 32>>>();
    scatter_kernel<<<Tn / 256, 256>>>();

    // shared expert: fused gate+up -> h (fp16) ; down -> out (f32)
    mma_gemm<true, false, false><<<dim3(In / 128, Tn / 128), 256, SMF>>>(
        xh, gsh, ush, hp, Hn, In);
    mma_gemm<false, false, false><<<dim3(Hn / 128, Tn / 128), 256, SMD>>>(
        hp, dsh, nullptr, out, In, Hn);

    // join: MoE weights ready
    cudaStreamWaitEvent(0, g_ss.evJoin, 0);

    // MoE: fused gathered gate+up -> h2 (fp16) ; down -> y2 (f32, per slot)
    mma_gemm<true, true, true><<<dim3(In / 128, Tn / 128, En), 256, SMF>>>(
        xh, gh, uh, h2p, Hn, In);
    mma_gemm<false, false, true><<<dim3(Hn / 128, Tn / 128, En), 256, SMD>>>(
        h2p, dh, nullptr, y2p, In, Hn);

    // combine: out += w0*y2[s0] + w1*y2[s1]
    size_t n4c = (size_t)Tn * Hn / 4;
    combine_kernel<<<(unsigned)((n4c + 255) / 256), 256>>>(out);
}

// round 11
// speedup vs baseline: 2.2429x; 1.0560x over previous
#include <cuda_runtime.h>
#include <cuda_fp16.h>
#include <cstdint>
#include <math.h>

#define Tn 4096
#define Hn 1024
#define In 2816
#define En 7

// ---------------- static scratch ----------------
__device__ __half xh_buf[(size_t)Tn * Hn];
__device__ __half wgs_h[(size_t)In * Hn];
__device__ __half wus_h[(size_t)In * Hn];
__device__ __half wds_h[(size_t)Hn * In];
__device__ __half wg_h[(size_t)En * In * Hn];
__device__ __half wu_h[(size_t)En * In * Hn];
__device__ __half wd_h[(size_t)En * Hn * In];
__device__ __half h_buf[(size_t)Tn * In];
__device__ __half h2_buf[(size_t)2 * Tn * In];
__device__ float  y2_buf[(size_t)2 * Tn * Hn];
__device__ float  dummy_logits[(size_t)Tn * En];

__device__ int   d_counts[En];
__device__ int   d_offsets[En];
__device__ int   d_cursor[En];
__device__ int   d_sel[Tn * 2];
__device__ float d_wgt[Tn * 2];
__device__ int   d_slot_token[2 * Tn];
__device__ int   d_token_slot[Tn * 2];

// ---------------- side stream (created at load time; streams/events are
// not device-memory allocations) ----------------
struct SideStream {
    cudaStream_t s2;
    cudaEvent_t  evFork, evRoute, evMoE;
    SideStream() {
        cudaStreamCreateWithFlags(&s2, cudaStreamNonBlocking);
        cudaEventCreateWithFlags(&evFork,  cudaEventDisableTiming);
        cudaEventCreateWithFlags(&evRoute, cudaEventDisableTiming);
        cudaEventCreateWithFlags(&evMoE,   cudaEventDisableTiming);
    }
};
static SideStream g_ss;

// ---------------- PTX helpers (portable, sm_80+) ----------------
__device__ __forceinline__ uint32_t smem_u32(const void* p) {
    uint32_t a;
    asm("{ .reg .u64 t; cvta.to.shared.u64 t, %1; cvt.u32.u64 %0, t; }" : "=r"(a) : "l"(p));
    return a;
}
__device__ __forceinline__ void cpasync16(uint32_t dst, const void* src) {
    asm volatile("cp.async.cg.shared.global [%0], [%1], 16;" :: "r"(dst), "l"(src) : "memory");
}
__device__ __forceinline__ void cpcommit() {
    asm volatile("cp.async.commit_group;" ::: "memory");
}
__device__ __forceinline__ void cpwait(int n) {
    if (n <= 0)      asm volatile("cp.async.wait_group 0;" ::: "memory");
    else if (n == 1) asm volatile("cp.async.wait_group 1;" ::: "memory");
    else             asm volatile("cp.async.wait_group 2;" ::: "memory");
}
__device__ __forceinline__ void ldsm_x4(uint32_t* r, uint32_t addr) {
    asm volatile("ldmatrix.sync.aligned.m8n8.x4.shared.b16 {%0,%1,%2,%3}, [%4];"
        : "=r"(r[0]), "=r"(r[1]), "=r"(r[2]), "=r"(r[3]) : "r"(addr));
}
__device__ __forceinline__ void ldsm_x2(uint32_t* r, uint32_t addr) {
    asm volatile("ldmatrix.sync.aligned.m8n8.x2.shared.b16 {%0,%1}, [%2];"
        : "=r"(r[0]), "=r"(r[1]) : "r"(addr));
}
// D(16x8) += A(16x16) * B(16x8) ; fp16 operands, f32 accum
__device__ __forceinline__ void mma16(float* c, const uint32_t* a, const uint32_t* b) {
    asm volatile(
        "mma.sync.aligned.m16n8k16.row.col.f32.f16.f16.f32 "
        "{%0,%1,%2,%3}, {%4,%5,%6,%7}, {%8,%9}, {%0,%1,%2,%3};\n"
        : "+f"(c[0]), "+f"(c[1]), "+f"(c[2]), "+f"(c[3])
        : "r"(a[0]), "r"(a[1]), "r"(a[2]), "r"(a[3]),
          "r"(b[0]), "r"(b[1]));
}

// ---------------- small kernels ----------------
__global__ void init_kernel() {
    int i = threadIdx.x;
    if (i < En) { d_counts[i] = 0; d_cursor[i] = 0; }
}

__global__ void f2h_kernel(const float* __restrict__ s, __half* __restrict__ d, size_t n4) {
    size_t i = (size_t)blockIdx.x * blockDim.x + threadIdx.x;
    if (i >= n4) return;
    float4 v = reinterpret_cast<const float4*>(s)[i];
    __half2 h0 = __floats2half2_rn(v.x, v.y);
    __half2 h1 = __floats2half2_rn(v.z, v.w);
    uint2 pk;
    pk.x = *reinterpret_cast<uint32_t*>(&h0);
    pk.y = *reinterpret_cast<uint32_t*>(&h1);
    reinterpret_cast<uint2*>(d)[i] = pk;
}

__global__ void routing_kernel(const float* __restrict__ x,
                               const float* __restrict__ Wr,
                               float* __restrict__ logits_out,
                               __half* __restrict__ xh) {
    int warp = threadIdx.x >> 5;
    int lane = threadIdx.x & 31;
    int t = blockIdx.x * (blockDim.x >> 5) + warp;
    if (t >= Tn) return;
    const float* xrow = x + (size_t)t * Hn;
    float acc[En];
#pragma unroll
    for (int e = 0; e < En; e++) acc[e] = 0.f;
    for (int k = lane; k < Hn; k += 32) {
        float xv = xrow[k];
        xh[(size_t)t * Hn + k] = __float2half_rn(xv);
#pragma unroll
        for (int e = 0; e < En; e++) acc[e] += xv * Wr[e * Hn + k];
    }
#pragma unroll
    for (int e = 0; e < En; e++) {
#pragma unroll
        for (int o = 16; o > 0; o >>= 1)
            acc[e] += __shfl_xor_sync(0xFFFFFFFFu, acc[e], o);
    }
    if (lane == 0) {
        int b0 = 0; float v0 = acc[0];
#pragma unroll
        for (int e = 1; e < En; e++) if (acc[e] > v0) { v0 = acc[e]; b0 = e; }
        int b1 = -1; float v1 = -1e30f;
#pragma unroll
        for (int e = 0; e < En; e++)
            if (e != b0 && acc[e] > v1) { v1 = acc[e]; b1 = e; }
        float w0 = 1.f / (1.f + expf(v1 - v0));
        float w1 = 1.f - w0;
        d_sel[t * 2 + 0] = b0; d_sel[t * 2 + 1] = b1;
        d_wgt[t * 2 + 0] = w0; d_wgt[t * 2 + 1] = w1;
        atomicAdd(&d_counts[b0], 1);
        atomicAdd(&d_counts[b1], 1);
#pragma unroll
        for (int e = 0; e < En; e++) logits_out[(size_t)t * En + e] = acc[e];
    }
}

__global__ void prefix_kernel() {
    if (threadIdx.x == 0) {
        int s = 0;
        for (int e = 0; e < En; e++) { d_offsets[e] = s; s += d_counts[e]; }
    }
}

__global__ void scatter_kernel() {
    int t = blockIdx.x * blockDim.x + threadIdx.x;
    if (t >= Tn) return;
#pragma unroll
    for (int k = 0; k < 2; k++) {
        int e = d_sel[t * 2 + k];
        int p = atomicAdd(&d_cursor[e], 1);
        int slot = d_offsets[e] + p;
        d_slot_token[slot] = t;
        d_token_slot[t * 2 + k] = slot;
    }
}

__global__ void combine_kernel(float* __restrict__ out) {
    size_t idx = (size_t)blockIdx.x * blockDim.x + threadIdx.x;
    size_t i = idx * 4;
    if (i >= (size_t)Tn * Hn) return;
    int t = (int)(i / Hn);
    int h = (int)(i % Hn);
    int s0 = d_token_slot[t * 2 + 0];
    int s1 = d_token_slot[t * 2 + 1];
    float w0 = d_wgt[t * 2 + 0];
    float w1 = d_wgt[t * 2 + 1];
    float4 o = *reinterpret_cast<float4*>(out + i);
    float4 a = *reinterpret_cast<const float4*>(y2_buf + (size_t)s0 * Hn + h);
    float4 b = *reinterpret_cast<const float4*>(y2_buf + (size_t)s1 * Hn + h);
    o.x += w0 * a.x + w1 * b.x;
    o.y += w0 * a.y + w1 * b.y;
    o.z += w0 * a.z + w1 * b.z;
    o.w += w0 * a.w + w1 * b.w;
    *reinterpret_cast<float4*>(out + i) = o;
}

// ---------------- fp16 mma.sync GEMM: BK=64, 4-stage, 1 sync/chunk ----------
// (byte-identical mainloop to round-8 winner)
#define TSTR 72                    // halves per smem row
#define TILEB (128 * TSTR * 2)     // 18432 B per tile
#define NSTAGE 4

template <bool FUSED, bool GATHER, bool EXPERT>
__global__ void __launch_bounds__(256, 1)
mma_gemm(const __half* __restrict__ A, const __half* __restrict__ W0,
         const __half* __restrict__ W1, void* __restrict__ Cv, int K, int ldC) {
    int rowBase = 0, segRows = Tn;
    const __half* W0p = W0;
    const __half* W1p = W1;
    if (EXPERT) {
        int e = blockIdx.z;
        rowBase = d_offsets[e];
        segRows = d_counts[e];
        size_t ws = (size_t)ldC * K;
        W0p = W0 + (size_t)e * ws;
        if (FUSED) W1p = W1 + (size_t)e * ws;
    }
    int byRow = blockIdx.y * 128;
    if (byRow >= segRows) return;
    int bx = blockIdx.x * 128;

    extern __shared__ char sm[];
    uint32_t sA = smem_u32(sm);
    const int NOP = FUSED ? 3 : 2;
    const uint32_t STAGEB = (uint32_t)(NOP * TILEB);

    int tid = threadIdx.x;
    int lane = tid & 31, wid = tid >> 5;
    int gid = lane >> 2, tig = lane & 3;
    int wm = wid & 1, wn = wid >> 1;

    int q_ = tid & 7;
    int row0 = tid >> 3;
    uint32_t dstB[4];
    const __half* aP[4];
    const __half* w0P[4];
    const __half* w1P[4];
#pragma unroll
    for (int it = 0; it < 4; it++) {
        int row = row0 + it * 32;
        dstB[it] = (uint32_t)(row * TSTR * 2 + q_ * 16);
        int lrow = byRow + row;
        int lcl = lrow < segRows ? lrow : (segRows - 1);
        int arow = GATHER ? d_slot_token[rowBase + lcl] : (rowBase + lcl);
        aP[it]  = A   + (size_t)arow * K + q_ * 8;
        w0P[it] = W0p + (size_t)(bx + row) * K + q_ * 8;
        if (FUSED) w1P[it] = W1p + (size_t)(bx + row) * K + q_ * 8;
    }

    uint32_t aOff[4];
#pragma unroll
    for (int mi = 0; mi < 4; mi++) {
        int rowA = wm * 64 + mi * 16 + (lane & 15);
        int colA = ((lane >> 4) & 1) * 8;
        aOff[mi] = (uint32_t)((rowA * TSTR + colA) * 2);
    }
    uint32_t bOff[4];
#pragma unroll
    for (int ni = 0; ni < 4; ni++) {
        int rowB = wn * 32 + ni * 8 + (lane & 7);
        int colB = ((lane >> 3) & 1) * 8;
        bOff[ni] = (uint32_t)((rowB * TSTR + colB) * 2);
    }

    float acc0[4][4][4];
    float acc1[4][4][4];
#pragma unroll
    for (int mi = 0; mi < 4; mi++)
#pragma unroll
        for (int ni = 0; ni < 4; ni++)
#pragma unroll
            for (int r = 0; r < 4; r++) { acc0[mi][ni][r] = 0.f; if (FUSED) acc1[mi][ni][r] = 0.f; }

    auto loadStage = [&](int j) {
        uint32_t st = sA + (uint32_t)(j % NSTAGE) * STAGEB;
        size_t koff = (size_t)j * 64;
#pragma unroll
        for (int it = 0; it < 4; it++)
            cpasync16(st + dstB[it], aP[it] + koff);
#pragma unroll
        for (int it = 0; it < 4; it++)
            cpasync16(st + (uint32_t)TILEB + dstB[it], w0P[it] + koff);
        if (FUSED) {
#pragma unroll
            for (int it = 0; it < 4; it++)
                cpasync16(st + (uint32_t)(2 * TILEB) + dstB[it], w1P[it] + koff);
        }
        cpcommit();
    };

    int NKS = K / 64;
    loadStage(0);
    loadStage(1);
    loadStage(2);

    for (int i = 0; i < NKS; i++) {
        int rem = NKS - 1 - i;
        cpwait(rem > 2 ? 2 : rem);
        __syncthreads();

        uint32_t stA = sA + (uint32_t)(i % NSTAGE) * STAGEB;
        uint32_t stB0 = stA + (uint32_t)TILEB;
        uint32_t stB1 = stA + (uint32_t)(2 * TILEB);

#pragma unroll
        for (int kk = 0; kk < 4; kk++) {
            uint32_t ko = (uint32_t)(kk * 32);
            uint32_t a[4][4];
#pragma unroll
            for (int mi = 0; mi < 4; mi++)
                ldsm_x4(a[mi], stA + aOff[mi] + ko);
            uint32_t b[4][2];
#pragma unroll
            for (int ni = 0; ni < 4; ni++)
                ldsm_x2(b[ni], stB0 + bOff[ni] + ko);
#pragma unroll
            for (int mi = 0; mi < 4; mi++)
#pragma unroll
                for (int ni = 0; ni < 4; ni++)
                    mma16(acc0[mi][ni], a[mi], b[ni]);
            if (FUSED) {
#pragma unroll
                for (int ni = 0; ni < 4; ni++)
                    ldsm_x2(b[ni], stB1 + bOff[ni] + ko);
#pragma unroll
                for (int mi = 0; mi < 4; mi++)
#pragma unroll
                    for (int ni = 0; ni < 4; ni++)
                        mma16(acc1[mi][ni], a[mi], b[ni]);
            }
        }
        if (i + 3 < NKS) loadStage(i + 3);
    }

    // ---- epilogue ----
#pragma unroll
    for (int mi = 0; mi < 4; mi++) {
        int lr0 = byRow + wm * 64 + mi * 16 + gid;
#pragma unroll
        for (int half = 0; half < 2; half++) {
            int lr = lr0 + half * 8;
            if (lr >= segRows) continue;
            size_t cbase = (size_t)(rowBase + lr) * ldC + bx + wn * 32 + 2 * tig;
            if (FUSED) {
                __half* Ch = (__half*)Cv;
#pragma unroll
                for (int ni = 0; ni < 4; ni++) {
                    float g0 = acc0[mi][ni][half * 2 + 0];
                    float g1 = acc0[mi][ni][half * 2 + 1];
                    float u0 = acc1[mi][ni][half * 2 + 0];
                    float u1 = acc1[mi][ni][half * 2 + 1];
                    float h0 = g0 / (1.f + expf(-g0)) * u0;
                    float h1 = g1 / (1.f + expf(-g1)) * u1;
                    *reinterpret_cast<__half2*>(Ch + cbase + ni * 8) =
                        __floats2half2_rn(h0, h1);
                }
            } else {
                float* Cf = (float*)Cv;
#pragma unroll
                for (int ni = 0; ni < 4; ni++)
                    *reinterpret_cast<float2*>(Cf + cbase + ni * 8) =
                        make_float2(acc0[mi][ni][half * 2 + 0], acc0[mi][ni][half * 2 + 1]);
            }
        }
    }
}

// ---------------- launch ----------------
extern "C" void kernel_launch(void* const* d_in, const int* in_sizes, int n_in,
                              void* d_out, int out_size) {
    const float* x    = (const float*)d_in[0];
    const float* Wg_s = (const float*)d_in[1];
    const float* Wu_s = (const float*)d_in[2];
    const float* Wd_s = (const float*)d_in[3];
    const float* Wg   = (const float*)d_in[4];
    const float* Wu   = (const float*)d_in[5];
    const float* Wd   = (const float*)d_in[6];
    const float* Wr   = (const float*)d_in[7];
    float* out = (float*)d_out;

    __half *xh, *gsh, *ush, *dsh, *gh, *uh, *dh, *hp, *h2p;
    float *y2p, *dlog;
    cudaGetSymbolAddress((void**)&xh,  xh_buf);
    cudaGetSymbolAddress((void**)&gsh, wgs_h);
    cudaGetSymbolAddress((void**)&ush, wus_h);
    cudaGetSymbolAddress((void**)&dsh, wds_h);
    cudaGetSymbolAddress((void**)&gh,  wg_h);
    cudaGetSymbolAddress((void**)&uh,  wu_h);
    cudaGetSymbolAddress((void**)&dh,  wd_h);
    cudaGetSymbolAddress((void**)&hp,  h_buf);
    cudaGetSymbolAddress((void**)&h2p, h2_buf);
    cudaGetSymbolAddress((void**)&y2p, y2_buf);
    cudaGetSymbolAddress((void**)&dlog, dummy_logits);

    bool has_logits = (out_size >= Tn * Hn + Tn * En);
    float* logits = has_logits ? (out + (size_t)Tn * Hn) : dlog;

    const int SMF = NSTAGE * 3 * TILEB;   // 221184 B
    const int SMD = NSTAGE * 2 * TILEB;   // 147456 B
    cudaFuncSetAttribute(mma_gemm<true,  false, false>, cudaFuncAttributeMaxDynamicSharedMemorySize, SMF);
    cudaFuncSetAttribute(mma_gemm<true,  true,  true >, cudaFuncAttributeMaxDynamicSharedMemorySize, SMF);
    cudaFuncSetAttribute(mma_gemm<false, false, false>, cudaFuncAttributeMaxDynamicSharedMemorySize, SMD);
    cudaFuncSetAttribute(mma_gemm<false, false, true >, cudaFuncAttributeMaxDynamicSharedMemorySize, SMD);

    auto convN = [&](const float* s, __half* d, size_t n, cudaStream_t st) {
        size_t n4 = n / 4;
        f2h_kernel<<<(unsigned)((n4 + 255) / 256), 256, 0, st>>>(s, d, n4);
    };

    // ================= dual-chain schedule =================
    // side stream: MoE weight convs -> (after routing) MoE GEMM chain
    // main stream: shared convs + routing -> shared GEMM chain -> combine
    // The two GEMM chains co-schedule: tail waves of one are backfilled by
    // CTAs of the other.
    cudaEventRecord(g_ss.evFork, 0);
    cudaStreamWaitEvent(g_ss.s2, g_ss.evFork, 0);

    // side: MoE weight conversions (~45us DRAM), overlapped with routing phase
    convN(Wg, gh, (size_t)En * In * Hn, g_ss.s2);
    convN(Wu, uh, (size_t)En * In * Hn, g_ss.s2);
    convN(Wd, dh, (size_t)En * Hn * In, g_ss.s2);

    // main: shared weight convs + routing pipeline
    convN(Wg_s, gsh, (size_t)In * Hn, 0);
    convN(Wu_s, ush, (size_t)In * Hn, 0);
    convN(Wd_s, dsh, (size_t)Hn * In, 0);
    init_kernel<<<1, 32>>>();
    routing_kernel<<<Tn / 4, 128>>>(x, Wr, logits, xh);
    prefix_kernel<<<1, 32>>>();
    scatter_kernel<<<Tn / 256, 256>>>();
    cudaEventRecord(g_ss.evRoute, 0);

    // side: MoE GEMM chain (needs routing results + its own convs)
    cudaStreamWaitEvent(g_ss.s2, g_ss.evRoute, 0);
    mma_gemm<true, true, true><<<dim3(In / 128, Tn / 128, En), 256, SMF, g_ss.s2>>>(
        xh, gh, uh, h2p, Hn, In);
    mma_gemm<false, false, true><<<dim3(Hn / 128, Tn / 128, En), 256, SMD, g_ss.s2>>>(
        h2p, dh, nullptr, y2p, In, Hn);
    cudaEventRecord(g_ss.evMoE, g_ss.s2);

    // main: shared-expert GEMM chain (concurrent with MoE chain)
    mma_gemm<true, false, false><<<dim3(In / 128, Tn / 128), 256, SMF>>>(
        xh, gsh, ush, hp, Hn, In);
    mma_gemm<false, false, false><<<dim3(Hn / 128, Tn / 128), 256, SMD>>>(
        hp, dsh, nullptr, out, In, Hn);

    // join + combine
    cudaStreamWaitEvent(0, g_ss.evMoE, 0);
    size_t n4c = (size_t)Tn * Hn / 4;
    combine_kernel<<<(unsigned)((n4c + 255) / 256), 256>>>(out);
}